// round 17
// baseline (speedup 1.0000x reference)
#include <cuda_runtime.h>
#include <cstddef>
#include <cstdint>

#define Bz 32
#define Nn 4096
#define Dd 256
#define Kk 8
#define NB 16              // n-chunks per batch in k_attn (256 rows each)

// ---------------- scratch (device globals; no allocations) -----------------
__device__ float  g_slots[Bz * Kk * Dd];
__device__ float  g_q[Bz * Kk * Dd];            // qg = SCALE * q' * ln_in_g
__device__ float  g_qs1[Bz * Kk];               // sum_e qg
__device__ float  g_qb[Bz * Kk];                // SCALE * q' . ln_in_b
__device__ float  g_aggp[(size_t)NB * Bz * Kk * Dd];  // partial sum_n (a*rs)*x
__device__ float  g_rsp[NB * Bz * Kk];          // partial sum_n a
__device__ float  g_s2p[NB * Bz * Kk];          // partial sum_n a*m*rs
__device__ float2 g_mr[(size_t)Bz * Nn];        // per emb row: (m*rs, rs)
// pair-interleaved transposed weights: Wt2[kp][j] = (W[j][2kp], W[j][2kp+1])
__device__ float2 g_wqk2p[(Dd / 2) * Dd];       // [ep][f]
__device__ float2 g_WvT2[(Dd / 2) * Dd];
__device__ float2 g_WihT2[(Dd / 2) * 3 * Dd];
__device__ float2 g_WhhT2[(Dd / 2) * 3 * Dd];
__device__ float2 g_W1T2[(Dd / 2) * Dd];
__device__ float2 g_W2T2[(Dd / 2) * Dd];

// ---------------- helpers ----------------------------------------------------
__device__ __forceinline__ void ffma2(float2& d, float2 a, float2 b) {
    asm("fma.rn.f32x2 %0, %1, %2, %0;"
        : "+l"(reinterpret_cast<unsigned long long&>(d))
        : "l"(reinterpret_cast<unsigned long long&>(a)),
          "l"(reinterpret_cast<unsigned long long&>(b)));
}

__device__ __forceinline__ void wred2(float& a, float& b) {
#pragma unroll
    for (int o = 16; o > 0; o >>= 1) {
        a += __shfl_xor_sync(0xffffffffu, a, o);
        b += __shfl_xor_sync(0xffffffffu, b, o);
    }
}

// LN over one 256-row in smem, one warp per row
__device__ __forceinline__ void ln_row(const float* __restrict__ in,
                                       float* __restrict__ out,
                                       const float* __restrict__ g,
                                       const float* __restrict__ bb, int lane) {
    float4 v1 = *(const float4*)(in + lane * 4);
    float4 v2 = *(const float4*)(in + 128 + lane * 4);
    float s = v1.x + v1.y + v1.z + v1.w + v2.x + v2.y + v2.z + v2.w;
    float ss = v1.x * v1.x + v1.y * v1.y + v1.z * v1.z + v1.w * v1.w
             + v2.x * v2.x + v2.y * v2.y + v2.z * v2.z + v2.w * v2.w;
    wred2(s, ss);
    float m = s * (1.f / 256.f);
    float rs = rsqrtf(ss * (1.f / 256.f) - m * m + 1e-5f);
    int d = lane * 4;
    float4 ga = *(const float4*)(g + d), ba = *(const float4*)(bb + d);
    out[d + 0] = (v1.x - m) * rs * ga.x + ba.x;
    out[d + 1] = (v1.y - m) * rs * ga.y + ba.y;
    out[d + 2] = (v1.z - m) * rs * ga.z + ba.z;
    out[d + 3] = (v1.w - m) * rs * ga.w + ba.w;
    int d2 = d + 128;
    float4 gb = *(const float4*)(g + d2), bbv = *(const float4*)(bb + d2);
    out[d2 + 0] = (v2.x - m) * rs * gb.x + bbv.x;
    out[d2 + 1] = (v2.y - m) * rs * gb.y + bbv.y;
    out[d2 + 2] = (v2.z - m) * rs * gb.z + bbv.z;
    out[d2 + 3] = (v2.w - m) * rs * gb.w + bbv.w;
}

// ---------------- merged setup: rowstats + slot init + 5 transposes ---------
#define RS_BLOCKS (Bz * Nn / 8)      // 16384
#define INIT_BLOCKS (Bz * Kk)        // 32
__global__ void __launch_bounds__(256) k_setup(
    const float* __restrict__ emb,
    const float* __restrict__ noise, const float* __restrict__ mu,
    const float* __restrict__ ls,
    const float* __restrict__ Wv, const float* __restrict__ W_ih,
    const float* __restrict__ W_hh, const float* __restrict__ W1,
    const float* __restrict__ W2) {
    __shared__ float t[32][33];
    int blk = blockIdx.x, tid = threadIdx.x;
    if (blk < RS_BLOCKS) {
        int row = blk * 8 + (tid >> 5);
        int lane = tid & 31;
        const float4* er = (const float4*)(emb + (size_t)row * 256);
        float4 v1 = er[lane];
        float4 v2 = er[lane + 32];
        float s = v1.x + v1.y + v1.z + v1.w + v2.x + v2.y + v2.z + v2.w;
        float ss = v1.x * v1.x + v1.y * v1.y + v1.z * v1.z + v1.w * v1.w
                 + v2.x * v2.x + v2.y * v2.y + v2.z * v2.z + v2.w * v2.w;
        wred2(s, ss);
        if (lane == 0) {
            float m = s * (1.f / 256.f);
            float rs = rsqrtf(ss * (1.f / 256.f) - m * m + 1e-5f);
            g_mr[row] = make_float2(m * rs, rs);
        }
        return;
    }
    if (blk < RS_BLOCKS + INIT_BLOCKS) {
        int i = (blk - RS_BLOCKS) * 256 + tid;
        int d = i & 255;
        g_slots[i] = mu[d] + expf(ls[d]) * noise[i];
        return;
    }
    int w = blk - (RS_BLOCKS + INIT_BLOCKS);
    const float* W; float2* Wt2; int J, lw;
    if (w < 64)       { W = Wv;   Wt2 = g_WvT2;  J = 256; lw = w; }
    else if (w < 256) { W = W_ih; Wt2 = g_WihT2; J = 768; lw = w - 64; }
    else if (w < 448) { W = W_hh; Wt2 = g_WhhT2; J = 768; lw = w - 256; }
    else if (w < 512) { W = W1;   Wt2 = g_W1T2;  J = 256; lw = w - 448; }
    else              { W = W2;   Wt2 = g_W2T2;  J = 256; lw = w - 512; }
    int j0 = (lw >> 3) * 32, k0 = (lw & 7) * 32;
    int x = tid & 31, y = tid >> 5;
#pragma unroll
    for (int yy = y; yy < 32; yy += 8)
        t[yy][x] = W[(size_t)(j0 + yy) * 256 + k0 + x];
    __syncthreads();
#pragma unroll
    for (int kp = y; kp < 16; kp += 8)
        Wt2[(size_t)(k0 / 2 + kp) * J + j0 + x] = make_float2(t[x][2 * kp], t[x][2 * kp + 1]);
}

// wqk2p[e/2][f] pairs of: sum_d Wq[d,e] * Wk[d,f]
__global__ void __launch_bounds__(256) k_wqk(const float* __restrict__ Wq,
                                             const float* __restrict__ Wk) {
    __shared__ float sq[32][33], sk[32][33];
    int be = blockIdx.x, bf = blockIdx.y, tid = threadIdx.x;
    int dd = tid >> 3, e4 = (tid & 7) * 4;
    int ff = tid & 31, eo = (tid >> 5) * 4;
    float acc[4] = {};
    for (int d0 = 0; d0 < 256; d0 += 32) {
        float4 q4 = *(const float4*)(Wq + (size_t)(d0 + dd) * 256 + be * 32 + e4);
        float4 k4 = *(const float4*)(Wk + (size_t)(d0 + dd) * 256 + bf * 32 + e4);
        sq[dd][e4 + 0] = q4.x; sq[dd][e4 + 1] = q4.y; sq[dd][e4 + 2] = q4.z; sq[dd][e4 + 3] = q4.w;
        sk[dd][e4 + 0] = k4.x; sk[dd][e4 + 1] = k4.y; sk[dd][e4 + 2] = k4.z; sk[dd][e4 + 3] = k4.w;
        __syncthreads();
#pragma unroll
        for (int d = 0; d < 32; d++) {
            float kv = sk[d][ff];
            acc[0] += sq[d][eo + 0] * kv;
            acc[1] += sq[d][eo + 1] * kv;
            acc[2] += sq[d][eo + 2] * kv;
            acc[3] += sq[d][eo + 3] * kv;
        }
        __syncthreads();
    }
    int ep = be * 16 + eo / 2, f = bf * 32 + ff;
    g_wqk2p[(size_t)ep * 256 + f]       = make_float2(acc[0], acc[1]);
    g_wqk2p[(size_t)(ep + 1) * 256 + f] = make_float2(acc[2], acc[3]);
}

// q-prep for iteration 0
__global__ void __launch_bounds__(256) k_prep0(const float* __restrict__ lslg,
                                               const float* __restrict__ lslb,
                                               const float* __restrict__ ling,
                                               const float* __restrict__ linb) {
    __shared__ __align__(16) float h[8][256], sn[8][256], qb_s[8][256];
    int b = blockIdx.x, tid = threadIdx.x, warp = tid >> 5, lane = tid & 31;
#pragma unroll
    for (int i = 0; i < 8; i++) {
        int idx = i * 256 + tid; int r = idx >> 8, e = idx & 255;
        h[r][e] = g_slots[(b * 8 + r) * 256 + e];
    }
    __syncthreads();
    ln_row(&h[warp][0], &sn[warp][0], lslg, lslb, lane);
    __syncthreads();
    int j = tid;
    float2 acc2[8] = {};
#pragma unroll 8
    for (int ep = 0; ep < 128; ep++) {
        float2 w2 = g_wqk2p[(size_t)ep * 256 + j];
#pragma unroll
        for (int r = 0; r < 8; r++)
            ffma2(acc2[r], w2, *(const float2*)&sn[r][2 * ep]);
    }
    float gv = ling[j] * 0.0625f, bv = linb[j] * 0.0625f;
#pragma unroll
    for (int r = 0; r < 8; r++) {
        float a = acc2[r].x + acc2[r].y;
        float qgv = a * gv;
        g_q[(b * 8 + r) * 256 + j] = qgv;
        h[r][j] = qgv;
        qb_s[r][j] = a * bv;
    }
    __syncthreads();
    float s1v = 0.f, s2v = 0.f;
#pragma unroll
    for (int i = 0; i < 8; i++) {
        s1v += h[warp][lane + 32 * i];
        s2v += qb_s[warp][lane + 32 * i];
    }
    wred2(s1v, s2v);
    if (lane == 0) { g_qs1[b * 8 + warp] = s1v; g_qb[b * 8 + warp] = s2v; }
}

// ---------------- streaming attention (broadcast-q dots) --------------------
struct AttnSmem {
    float4 qq[512];         // qq[e*2+j]: j=0 -> slots0-3 at e, j=1 -> slots4-7
    float  xt[64][260];
    float2 mrs[64];
    float2 at42[64][4];     // a * rs, packed slot pairs
    float2 ds[2][64][4];    // partial dots per elem-half
    float  rs_s[64][8];
    float  s2_s[64][8];
};

__global__ void __launch_bounds__(256) k_attn(const float* __restrict__ emb,
                                              float* __restrict__ attn_out) {
    extern __shared__ char smraw[];
    AttnSmem* S = (AttnSmem*)smraw;
    int b = blockIdx.y, nb = blockIdx.x, tid = threadIdx.x;

    {   // build slot-quad-interleaved q: qq[e*2+j]
        int e = tid;
        const float* qsrc = g_q + b * 8 * 256;
        S->qq[e * 2 + 0] = make_float4(qsrc[0 * 256 + e], qsrc[1 * 256 + e],
                                       qsrc[2 * 256 + e], qsrc[3 * 256 + e]);
        S->qq[e * 2 + 1] = make_float4(qsrc[4 * 256 + e], qsrc[5 * 256 + e],
                                       qsrc[6 * 256 + e], qsrc[7 * 256 + e]);
    }
    // softmax constants (threads 0..63 use them)
    float qs1k[8], qbk[8];
#pragma unroll
    for (int k = 0; k < 8; k++) { qs1k[k] = g_qs1[b * 8 + k]; qbk[k] = g_qb[b * 8 + k]; }

    const float* esrc = emb + ((size_t)b * Nn + nb * 256) * 256;
    const float2* msrc = g_mr + (size_t)b * Nn + nb * 256;

    float2 aggr2[8] = {};     // thread (tid<128) owns cols 2*tid, 2*tid+1 for 8 slots
    float rsl[8] = {}, s2l[8] = {};

    int w = tid >> 5, lane = tid & 31;
    int h = w & 1, g = w >> 1;          // dots mapping (tid < 128)
    int drow = g * 32 + lane;

    for (int t = 0; t < 4; t++) {
        // ---- stage 64 raw rows + stats (all 256 threads) ----
        const float* src = esrc + (size_t)t * 64 * 256;
#pragma unroll
        for (int i = 0; i < 16; i++) {
            int pp = tid + i * 256; int r = pp >> 6, c4 = pp & 63;
            *(float4*)&S->xt[r][c4 * 4] = *(const float4*)(src + r * 256 + c4 * 4);
        }
        if (tid < 64) S->mrs[tid] = msrc[t * 64 + tid];
        __syncthreads();

        // ---- dots: warp = 32 rows x 8 slots, elem-half h; q is broadcast ----
        if (tid < 128) {
            const float4* xr = (const float4*)&S->xt[drow][h * 128];
            const float4* qp4 = &S->qq[(h * 128) * 2];
            float2 aA0 = {}, aA1 = {}, aA2 = {}, aA3 = {};
            float2 aB0 = {}, aB1 = {}, aB2 = {}, aB3 = {};
#pragma unroll 8
            for (int c = 0; c < 32; c++) {
                float4 xa = xr[c];
                const float4* qc = qp4 + c * 8;
                float4 q0 = qc[0], q1 = qc[1];
                float2 x0 = make_float2(xa.x, xa.x);
                ffma2(aA0, make_float2(q0.x, q0.y), x0);
                ffma2(aA1, make_float2(q0.z, q0.w), x0);
                ffma2(aA2, make_float2(q1.x, q1.y), x0);
                ffma2(aA3, make_float2(q1.z, q1.w), x0);
                float4 q2 = qc[2], q3 = qc[3];
                float2 x1 = make_float2(xa.y, xa.y);
                ffma2(aB0, make_float2(q2.x, q2.y), x1);
                ffma2(aB1, make_float2(q2.z, q2.w), x1);
                ffma2(aB2, make_float2(q3.x, q3.y), x1);
                ffma2(aB3, make_float2(q3.z, q3.w), x1);
                float4 q4 = qc[4], q5 = qc[5];
                float2 x2 = make_float2(xa.z, xa.z);
                ffma2(aA0, make_float2(q4.x, q4.y), x2);
                ffma2(aA1, make_float2(q4.z, q4.w), x2);
                ffma2(aA2, make_float2(q5.x, q5.y), x2);
                ffma2(aA3, make_float2(q5.z, q5.w), x2);
                float4 q6 = qc[6], q7 = qc[7];
                float2 x3 = make_float2(xa.w, xa.w);
                ffma2(aB0, make_float2(q6.x, q6.y), x3);
                ffma2(aB1, make_float2(q6.z, q6.w), x3);
                ffma2(aB2, make_float2(q7.x, q7.y), x3);
                ffma2(aB3, make_float2(q7.z, q7.w), x3);
            }
            S->ds[h][drow][0] = make_float2(aA0.x + aB0.x, aA0.y + aB0.y);
            S->ds[h][drow][1] = make_float2(aA1.x + aB1.x, aA1.y + aB1.y);
            S->ds[h][drow][2] = make_float2(aA2.x + aB2.x, aA2.y + aB2.y);
            S->ds[h][drow][3] = make_float2(aA3.x + aB3.x, aA3.y + aB3.y);
        }
        __syncthreads();

        // ---- softmax: thread = one row, all 8 slots local (no shuffles) ----
        if (tid < 64) {
            int row = tid;
            float2 mr = S->mrs[row];
            const float4* d0 = (const float4*)&S->ds[0][row][0];
            const float4* d1 = (const float4*)&S->ds[1][row][0];
            float4 u0 = d0[0], u1 = d0[1], v0 = d1[0], v1 = d1[1];
            float dv[8];
            dv[0] = mr.y * (u0.x + v0.x) - mr.x * qs1k[0] + qbk[0];
            dv[1] = mr.y * (u0.y + v0.y) - mr.x * qs1k[1] + qbk[1];
            dv[2] = mr.y * (u0.z + v0.z) - mr.x * qs1k[2] + qbk[2];
            dv[3] = mr.y * (u0.w + v0.w) - mr.x * qs1k[3] + qbk[3];
            dv[4] = mr.y * (u1.x + v1.x) - mr.x * qs1k[4] + qbk[4];
            dv[5] = mr.y * (u1.y + v1.y) - mr.x * qs1k[5] + qbk[5];
            dv[6] = mr.y * (u1.z + v1.z) - mr.x * qs1k[6] + qbk[6];
            dv[7] = mr.y * (u1.w + v1.w) - mr.x * qs1k[7] + qbk[7];
            float mx = dv[0];
#pragma unroll
            for (int k = 1; k < 8; k++) mx = fmaxf(mx, dv[k]);
            float ex[8], sm = 0.f;
#pragma unroll
            for (int k = 0; k < 8; k++) { ex[k] = expf(dv[k] - mx); sm += ex[k]; }
            float inv = 1.f / sm;
            float a[8];
#pragma unroll
            for (int k = 0; k < 8; k++) {
                a[k] = ex[k] * inv + 1e-8f;
                rsl[k] += a[k];
                s2l[k] += a[k] * mr.x;
            }
            S->at42[row][0] = make_float2(a[0] * mr.y, a[1] * mr.y);
            S->at42[row][1] = make_float2(a[2] * mr.y, a[3] * mr.y);
            S->at42[row][2] = make_float2(a[4] * mr.y, a[5] * mr.y);
            S->at42[row][3] = make_float2(a[6] * mr.y, a[7] * mr.y);
        }
        __syncthreads();

        // ---- optional attn_vis write (recover a = at4 / rs) ----
        if (attn_out) {
            int k2 = tid >> 5, n2 = tid & 31;
            const float* a4 = (const float*)&S->at42[0][0];
            size_t o = (size_t)(b * 8 + k2) * Nn + nb * 256 + t * 64;
            attn_out[o + n2]      = a4[n2 * 8 + k2] / S->mrs[n2].y;
            attn_out[o + 32 + n2] = a4[(n2 + 32) * 8 + k2] / S->mrs[n2 + 32].y;
        }

        // ---- agg: thread (tid<128) owns cols 2t,2t+1; at42 broadcast ----
        if (tid < 128) {
            int e2 = tid * 2;
#pragma unroll 8
            for (int n = 0; n < 64; n++) {
                float2 xv = *(const float2*)&S->xt[n][e2];
                float4 a0 = *(const float4*)&S->at42[n][0];
                float4 a1 = *(const float4*)&S->at42[n][2];
                ffma2(aggr2[0], make_float2(a0.x, a0.x), xv);
                ffma2(aggr2[1], make_float2(a0.y, a0.y), xv);
                ffma2(aggr2[2], make_float2(a0.z, a0.z), xv);
                ffma2(aggr2[3], make_float2(a0.w, a0.w), xv);
                ffma2(aggr2[4], make_float2(a1.x, a1.x), xv);
                ffma2(aggr2[5], make_float2(a1.y, a1.y), xv);
                ffma2(aggr2[6], make_float2(a1.z, a1.z), xv);
                ffma2(aggr2[7], make_float2(a1.w, a1.w), xv);
            }
        }
        __syncthreads();
    }

    // ---- deterministic reductions + writeback ----
    if (tid < 64) {
#pragma unroll
        for (int k = 0; k < 8; k++) { S->rs_s[tid][k] = rsl[k]; S->s2_s[tid][k] = s2l[k]; }
    }
    __syncthreads();
    if (tid < 8) {
        float s = 0.f, s2 = 0.f;
#pragma unroll
        for (int i = 0; i < 64; i++) { s += S->rs_s[i][tid]; s2 += S->s2_s[i][tid]; }
        g_rsp[(nb * Bz + b) * 8 + tid] = s;
        g_s2p[(nb * Bz + b) * 8 + tid] = s2;
    }
    if (tid < 128) {
        size_t base = (size_t)(nb * Bz + b) * 8 * 256;
        int e2 = tid * 2;
#pragma unroll
        for (int k = 0; k < 8; k++)
            *(float2*)&g_aggp[base + k * 256 + e2] = aggr2[k];
    }
}

// ---------------- fused: reduce -> upd -> GRU -> LN -> MLP -> next q' ------
// grid (Bz, 4): 2 slot-rows per block; 512 threads, K split in halves.
struct FusedSmem {
    float ag[2][256], h[2][256], us[2][256], snew[2][256], sn[2][256];
    float p0[2][2][256], p1[2][2][256], p2[2][2][256], p3[2][2][256];
    float s1[2], s2[2], rinv[2];
};

__global__ void __launch_bounds__(512) k_fused(
    const float* __restrict__ b_ih, const float* __restrict__ b_hh,
    const float* __restrict__ b1, const float* __restrict__ b2,
    const float* __restrict__ lffg, const float* __restrict__ lffb,
    const float* __restrict__ lslg, const float* __restrict__ lslb,
    const float* __restrict__ ling, const float* __restrict__ linb,
    float* __restrict__ out_slots, int do_prep) {
    extern __shared__ char smem_raw[];
    FusedSmem* S = (FusedSmem*)smem_raw;
    int b = blockIdx.x, r0 = blockIdx.y * 2, tid = threadIdx.x;
    int j = tid & 255, hf = tid >> 8, kq0 = hf * 64;
    int warp = tid >> 5, lane = tid & 31;
    int rr_ = tid >> 8, ee_ = tid & 255;   // one (row, elem) per thread

    // ---- stage a: reduce partials, load slots ----
    if (tid < 2) {
        float s1 = 0.f, s2 = 0.f;
#pragma unroll
        for (int nb = 0; nb < NB; nb++) {
            s1 += g_rsp[(nb * Bz + b) * 8 + r0 + tid];
            s2 += g_s2p[(nb * Bz + b) * 8 + r0 + tid];
        }
        S->s1[tid] = s1; S->s2[tid] = s2; S->rinv[tid] = 1.f / s1;
    }
    {
        float a = 0.f;
#pragma unroll
        for (int nb = 0; nb < NB; nb++)
            a += g_aggp[((size_t)(nb * Bz + b) * 8 + r0 + rr_) * 256 + ee_];
        S->ag[rr_][ee_] = a;
        S->h[rr_][ee_] = g_slots[(b * 8 + r0 + rr_) * 256 + ee_];
    }
    __syncthreads();
    S->ag[rr_][ee_] = ling[ee_] * (S->ag[rr_][ee_] - S->s2[rr_]) + linb[ee_] * S->s1[rr_];
    __syncthreads();

    // ---- stage b: us = (agg @ Wv^T) / rowsum ----
    {
        float2 acc2[2] = {};
#pragma unroll 8
        for (int kp = 0; kp < 64; kp++) {
            float2 w2 = g_WvT2[(size_t)(kq0 + kp) * 256 + j];
#pragma unroll
            for (int r = 0; r < 2; r++)
                ffma2(acc2[r], w2, *(const float2*)&S->ag[r][2 * (kq0 + kp)]);
        }
#pragma unroll
        for (int r = 0; r < 2; r++) S->p0[hf][r][j] = acc2[r].x + acc2[r].y;
    }
    __syncthreads();
    S->us[rr_][ee_] = (S->p0[0][rr_][ee_] + S->p0[1][rr_][ee_]) * S->rinv[rr_];
    __syncthreads();

    // ---- stage c: all three GRU gates in one k-pass ----
    {
        float2 racc[2] = {}, zacc[2] = {}, nai[2] = {}, nah[2] = {};
#pragma unroll 4
        for (int kp = 0; kp < 64; kp++) {
            const float2* wi = g_WihT2 + (size_t)(kq0 + kp) * 768;
            const float2* wh = g_WhhT2 + (size_t)(kq0 + kp) * 768;
            float2 wir = wi[j], wiz = wi[256 + j], win = wi[512 + j];
            float2 whr = wh[j], whz = wh[256 + j], whn = wh[512 + j];
#pragma unroll
            for (int r = 0; r < 2; r++) {
                float2 u2 = *(const float2*)&S->us[r][2 * (kq0 + kp)];
                float2 h2 = *(const float2*)&S->h[r][2 * (kq0 + kp)];
                ffma2(racc[r], wir, u2); ffma2(racc[r], whr, h2);
                ffma2(zacc[r], wiz, u2); ffma2(zacc[r], whz, h2);
                ffma2(nai[r],  win, u2); ffma2(nah[r],  whn, h2);
            }
        }
#pragma unroll
        for (int r = 0; r < 2; r++) {
            S->p0[hf][r][j] = racc[r].x + racc[r].y;
            S->p1[hf][r][j] = zacc[r].x + zacc[r].y;
            S->p2[hf][r][j] = nai[r].x + nai[r].y;
            S->p3[hf][r][j] = nah[r].x + nah[r].y;
        }
    }
    __syncthreads();
    {
        float rr = 1.f / (1.f + expf(-(S->p0[0][rr_][ee_] + S->p0[1][rr_][ee_] + b_ih[ee_] + b_hh[ee_])));
        float zz = 1.f / (1.f + expf(-(S->p1[0][rr_][ee_] + S->p1[1][rr_][ee_] + b_ih[256 + ee_] + b_hh[256 + ee_])));
        float nn = tanhf(S->p2[0][rr_][ee_] + S->p2[1][rr_][ee_] + b_ih[512 + ee_]
                         + rr * (S->p3[0][rr_][ee_] + S->p3[1][rr_][ee_] + b_hh[512 + ee_]));
        S->snew[rr_][ee_] = (1.f - zz) * nn + zz * S->h[rr_][ee_];
    }
    __syncthreads();

    // ---- stage d: LN(snew) -> sn ----
    if (warp < 2) ln_row(&S->snew[warp][0], &S->sn[warp][0], lffg, lffb, lane);
    __syncthreads();

    // ---- stage e: MLP1 (leaky relu) ----
    {
        float2 acc2[2] = {};
#pragma unroll 8
        for (int kp = 0; kp < 64; kp++) {
            float2 w2 = g_W1T2[(size_t)(kq0 + kp) * 256 + j];
#pragma unroll
            for (int r = 0; r < 2; r++)
                ffma2(acc2[r], w2, *(const float2*)&S->sn[r][2 * (kq0 + kp)]);
        }
#pragma unroll
        for (int r = 0; r < 2; r++) S->p0[hf][r][j] = acc2[r].x + acc2[r].y;
    }
    __syncthreads();
    {
        float t = S->p0[0][rr_][ee_] + S->p0[1][rr_][ee_] + b1[ee_];
        S->ag[rr_][ee_] = (t > 0.f) ? t : 0.01f * t;
    }
    __syncthreads();

    // ---- stage f: MLP2 + residual -> slots ----
    {
        float2 acc2[2] = {};
#pragma unroll 8
        for (int kp = 0; kp < 64; kp++) {
            float2 w2 = g_W2T2[(size_t)(kq0 + kp) * 256 + j];
#pragma unroll
            for (int r = 0; r < 2; r++)
                ffma2(acc2[r], w2, *(const float2*)&S->ag[r][2 * (kq0 + kp)]);
        }
#pragma unroll
        for (int r = 0; r < 2; r++) S->p0[hf][r][j] = acc2[r].x + acc2[r].y;
    }
    __syncthreads();
    {
        float o = S->snew[rr_][ee_] + S->p0[0][rr_][ee_] + S->p0[1][rr_][ee_] + b2[ee_];
        g_slots[(b * 8 + r0 + rr_) * 256 + ee_] = o;
        if (out_slots) out_slots[(b * 8 + r0 + rr_) * 256 + ee_] = o;
        S->h[rr_][ee_] = o;
    }
    __syncthreads();

    // ---- stage g: prep next iteration's qg / qs1 / qb ----
    if (do_prep) {
        if (warp < 2) ln_row(&S->h[warp][0], &S->sn[warp][0], lslg, lslb, lane);
        __syncthreads();
        {
            float2 acc2[2] = {};
#pragma unroll 8
            for (int kp = 0; kp < 64; kp++) {
                float2 w2 = g_wqk2p[(size_t)(kq0 + kp) * 256 + j];
#pragma unroll
                for (int r = 0; r < 2; r++)
                    ffma2(acc2[r], w2, *(const float2*)&S->sn[r][2 * (kq0 + kp)]);
            }
#pragma unroll
            for (int r = 0; r < 2; r++) S->p0[hf][r][j] = acc2[r].x + acc2[r].y;
        }
        __syncthreads();
        {
            float qp = S->p0[0][rr_][ee_] + S->p0[1][rr_][ee_];
            float qgv = 0.0625f * qp * ling[ee_];
            g_q[(b * 8 + r0 + rr_) * 256 + ee_] = qgv;
            S->us[rr_][ee_] = qgv;
            S->snew[rr_][ee_] = 0.0625f * qp * linb[ee_];
        }
        __syncthreads();
        if (warp < 2) {
            float s1v = 0.f, s2v = 0.f;
#pragma unroll
            for (int i = 0; i < 8; i++) {
                s1v += S->us[warp][lane + 32 * i];
                s2v += S->snew[warp][lane + 32 * i];
            }
            wred2(s1v, s2v);
            if (lane == 0) {
                g_qs1[b * 8 + r0 + warp] = s1v;
                g_qb[b * 8 + r0 + warp] = s2v;
            }
        }
    }
}

// ---------------- launch ------------------------------------------------------
extern "C" void kernel_launch(void* const* d_in, const int* in_sizes, int n_in,
                              void* d_out, int out_size) {
    const float* emb   = (const float*)d_in[0];
    const float* noise = (const float*)d_in[1];
    const float* mu    = (const float*)d_in[2];
    const float* ls    = (const float*)d_in[3];
    const float* Wq    = (const float*)d_in[4];
    const float* Wk    = (const float*)d_in[5];
    const float* Wv    = (const float*)d_in[6];
    const float* W_ih  = (const float*)d_in[7];
    const float* W_hh  = (const float*)d_in[8];
    const float* b_ih  = (const float*)d_in[9];
    const float* b_hh  = (const float*)d_in[10];
    const float* W1    = (const float*)d_in[11];
    const float* b1    = (const float*)d_in[12];
    const float* W2    = (const float*)d_in[13];
    const float* b2    = (const float*)d_in[14];
    const float* lin_g = (const float*)d_in[15];
    const float* lin_b = (const float*)d_in[16];
    const float* lsl_g = (const float*)d_in[17];
    const float* lsl_b = (const float*)d_in[18];
    const float* lff_g = (const float*)d_in[19];
    const float* lff_b = (const float*)d_in[20];

    float* out       = (float*)d_out;
    float* out_slots = out;                  // [B,K,D]
    float* out_attn  = out + Bz * Kk * Dd;   // [B,K,N]

    cudaFuncSetAttribute(k_attn, cudaFuncAttributeMaxDynamicSharedMemorySize,
                         (int)sizeof(AttnSmem));
    cudaFuncSetAttribute(k_fused, cudaFuncAttributeMaxDynamicSharedMemorySize,
                         (int)sizeof(FusedSmem));

    k_setup<<<RS_BLOCKS + INIT_BLOCKS + 576, 256>>>(
        emb, noise, mu, ls, Wv, W_ih, W_hh, W1, W2);
    k_wqk<<<dim3(8, 8), 256>>>(Wq, Wk);
    k_prep0<<<Bz, 256>>>(lsl_g, lsl_b, lin_g, lin_b);

    for (int it = 0; it < 3; it++) {
        k_attn<<<dim3(NB, Bz), 256, sizeof(AttnSmem)>>>(
            emb, (it == 2) ? out_attn : nullptr);
        k_fused<<<dim3(Bz, 4), 512, sizeof(FusedSmem)>>>(
            b_ih, b_hh, b1, b2, lff_g, lff_b, lsl_g, lsl_b, lin_g, lin_b,
            (it == 2) ? out_slots : nullptr, (it < 2) ? 1 : 0);
    }
}